// round 1
// baseline (speedup 1.0000x reference)
#include <cuda_runtime.h>
#include <math.h>

#define N_V    100000
#define NE_    20000
#define NNZ_   1600000
#define NFEAT_ 128
#define NHID_  64
#define NCLASS_ 40
#define NLAYER_ 4

// ---------------- device scratch (static, no allocation) ----------------
__device__ float g_X [N_V * NHID_];   // current features (also Xi in-place)
__device__ float g_X0[N_V * NHID_];   // residual anchor
__device__ float g_Xe[NE_ * NHID_];   // edge features (pre-scaled by degE/count)
__device__ float g_escale[NE_];
__device__ int   g_cntE[NE_];
__device__ int   g_cntV[N_V];
__device__ int   g_offE[NE_ + 1];
__device__ int   g_offV[N_V + 1];
__device__ int   g_adjE[NNZ_];        // members (vertex ids) per edge, CSR
__device__ int   g_adjV[NNZ_];        // incident edges per vertex, CSC

// ---------------- CSR build ----------------
__global__ void zero_cnt_k() {
    int i = blockIdx.x * blockDim.x + threadIdx.x;
    if (i < NE_) g_cntE[i] = 0;
    if (i < N_V) g_cntV[i] = 0;
}

__global__ void hist_k(const int* __restrict__ vertex, const int* __restrict__ edges) {
    int i = blockIdx.x * blockDim.x + threadIdx.x;
    if (i < NNZ_) {
        atomicAdd(&g_cntE[edges[i]], 1);
        atomicAdd(&g_cntV[vertex[i]], 1);
    }
}

__global__ void escale_k(const float* __restrict__ degE) {
    int i = blockIdx.x * blockDim.x + threadIdx.x;
    if (i < NE_)
        g_escale[i] = degE[i] / fmaxf((float)g_cntE[i], 1.0f);
}

// single-block exclusive scan (sel=0: edges, sel=1: vertices)
__global__ void __launch_bounds__(1024) scan_excl_k(int sel) {
    const int* cnt = sel ? g_cntV : g_cntE;
    int* off       = sel ? g_offV : g_offE;
    int n          = sel ? N_V : NE_;
    __shared__ int wsum[32];
    __shared__ int s_run;
    int tid = threadIdx.x, lane = tid & 31, wid = tid >> 5;
    if (tid == 0) s_run = 0;
    __syncthreads();
    for (int base = 0; base < n; base += 1024) {
        int i = base + tid;
        int x = (i < n) ? cnt[i] : 0;
        int inc = x;
        #pragma unroll
        for (int o = 1; o < 32; o <<= 1) {
            int t = __shfl_up_sync(0xffffffffu, inc, o);
            if (lane >= o) inc += t;
        }
        if (lane == 31) wsum[wid] = inc;
        __syncthreads();
        int run = s_run;
        int woff = 0;
        for (int w = 0; w < wid; w++) woff += wsum[w];
        if (i < n) off[i] = run + woff + inc - x;
        __syncthreads();
        if (tid == 1023) s_run = run + woff + inc;  // tile total carried forward
    }
    __syncthreads();
    if (tid == 0) off[n] = s_run;
}

__global__ void build_adj_k(const int* __restrict__ vertex, const int* __restrict__ edges) {
    int i = blockIdx.x * blockDim.x + threadIdx.x;
    if (i < NNZ_) {
        int v = vertex[i], e = edges[i];
        int pe = g_offE[e] + atomicAdd(&g_cntE[e], 1);
        g_adjE[pe] = v;
        int pv = g_offV[v] + atomicAdd(&g_cntV[v], 1);
        g_adjV[pv] = e;
    }
}

// ---------------- aggregation (gather, no atomics) ----------------
// vertex -> edge mean (pre-scaled by degE/count)
__global__ void __launch_bounds__(64) agg_ve_k() {
    int e = blockIdx.x;
    int f = threadIdx.x;
    int beg = g_offE[e], end = g_offE[e + 1];
    __shared__ int sidx[64];
    float acc = 0.f;
    for (int base = beg; base < end; base += 64) {
        int m = end - base; if (m > 64) m = 64;
        __syncthreads();
        if (f < m) sidx[f] = g_adjE[base + f];
        __syncthreads();
        #pragma unroll 4
        for (int j = 0; j < m; j++)
            acc += __ldg(&g_X[sidx[j] * NHID_ + f]);
    }
    g_Xe[e * NHID_ + f] = acc * g_escale[e];
}

// edge -> vertex sum, fused: *degV, L2 normalize, Xi = 0.9*Xn + 0.1*X0 (in-place into g_X)
__global__ void __launch_bounds__(64) agg_ev_k(const float* __restrict__ degV) {
    int v = blockIdx.x;
    int f = threadIdx.x;
    int beg = g_offV[v], end = g_offV[v + 1];
    __shared__ int sidx[64];
    __shared__ float redsm[2];
    float acc = 0.f;
    for (int base = beg; base < end; base += 64) {
        int m = end - base; if (m > 64) m = 64;
        __syncthreads();
        if (f < m) sidx[f] = g_adjV[base + f];
        __syncthreads();
        #pragma unroll 4
        for (int j = 0; j < m; j++)
            acc += __ldg(&g_Xe[sidx[j] * NHID_ + f]);
    }
    acc *= __ldg(&degV[v]);
    float ss = acc * acc;
    #pragma unroll
    for (int o = 16; o; o >>= 1) ss += __shfl_xor_sync(0xffffffffu, ss, o);
    if ((f & 31) == 0) redsm[f >> 5] = ss;
    __syncthreads();
    float tot = redsm[0] + redsm[1];
    float scale = (tot > 0.f) ? rsqrtf(tot) : 0.f;
    g_X[v * NHID_ + f] = 0.9f * acc * scale + 0.1f * g_X0[v * NHID_ + f];
}

// ---------------- tiled GEMM (64 rows x NCOL), K chunked by 64 ----------------
// MODE 0: X = relu(A@W + b), also copy to X0.  (A = external x, K=128, NCOL=64)
// MODE 1: X = relu(c0*Xi + c1*(Xi@W)), in-place on g_X. (K=NCOL=64)
// MODE 2: out = log_softmax(g_X@W + b).         (K=64, NCOL=40)
template <int K, int NCOL, int MODE>
__global__ void __launch_bounds__(256) gemm_k(
    const float* __restrict__ Aext, const float* __restrict__ W,
    const float* __restrict__ bias, float* __restrict__ outext,
    float c0, float c1)
{
    constexpr int KC = 64;
    constexpr int KP = KC + 4;
    constexpr int NP = (NCOL + 7) & ~3;  // 64->68, 40->44 (16B aligned rows)
    __shared__ float As[64 * KP];
    __shared__ float Wsm[KC * NP];
    __shared__ float Ls[(MODE == 2) ? 64 * NCOL : 1];

    const float* A = (MODE == 0) ? Aext : g_X;
    const int M = N_V;
    int tid = threadIdx.x;
    int row0 = blockIdx.x * 64;
    int tx = tid & 15, ty = tid >> 4;
    bool active = (NCOL == 64) || (tx * 4 < NCOL);

    float acc[4][4] = {};

    for (int kc = 0; kc < K; kc += KC) {
        for (int idx = tid; idx < KC * NCOL; idx += 256) {
            int k = idx / NCOL, c = idx - k * NCOL;
            Wsm[k * NP + c] = W[(kc + k) * NCOL + c];
        }
        for (int idx = tid; idx < 64 * KC; idx += 256) {
            int r = idx >> 6, k = idx & 63;
            int row = row0 + r;
            As[r * KP + k] = (row < M) ? A[(size_t)row * K + kc + k] : 0.f;
        }
        __syncthreads();
        if (active) {
            #pragma unroll 8
            for (int k = 0; k < KC; k++) {
                float4 w = *(const float4*)&Wsm[k * NP + tx * 4];
                float a0 = As[(ty * 4 + 0) * KP + k];
                float a1 = As[(ty * 4 + 1) * KP + k];
                float a2 = As[(ty * 4 + 2) * KP + k];
                float a3 = As[(ty * 4 + 3) * KP + k];
                acc[0][0] += a0 * w.x; acc[0][1] += a0 * w.y; acc[0][2] += a0 * w.z; acc[0][3] += a0 * w.w;
                acc[1][0] += a1 * w.x; acc[1][1] += a1 * w.y; acc[1][2] += a1 * w.z; acc[1][3] += a1 * w.w;
                acc[2][0] += a2 * w.x; acc[2][1] += a2 * w.y; acc[2][2] += a2 * w.z; acc[2][3] += a2 * w.w;
                acc[3][0] += a3 * w.x; acc[3][1] += a3 * w.y; acc[3][2] += a3 * w.z; acc[3][3] += a3 * w.w;
            }
        }
        __syncthreads();
    }

    if (MODE == 0) {
        float bx = __ldg(bias + tx * 4 + 0), by = __ldg(bias + tx * 4 + 1);
        float bz = __ldg(bias + tx * 4 + 2), bw = __ldg(bias + tx * 4 + 3);
        #pragma unroll
        for (int i = 0; i < 4; i++) {
            int row = row0 + ty * 4 + i;
            if (row < M) {
                float4 r4;
                r4.x = fmaxf(acc[i][0] + bx, 0.f);
                r4.y = fmaxf(acc[i][1] + by, 0.f);
                r4.z = fmaxf(acc[i][2] + bz, 0.f);
                r4.w = fmaxf(acc[i][3] + bw, 0.f);
                *(float4*)&g_X [(size_t)row * NHID_ + tx * 4] = r4;
                *(float4*)&g_X0[(size_t)row * NHID_ + tx * 4] = r4;
            }
        }
    } else if (MODE == 1) {
        #pragma unroll
        for (int i = 0; i < 4; i++) {
            int r = ty * 4 + i;
            int row = row0 + r;
            if (row < M) {
                float4 r4;
                r4.x = fmaxf(c0 * As[r * KP + tx * 4 + 0] + c1 * acc[i][0], 0.f);
                r4.y = fmaxf(c0 * As[r * KP + tx * 4 + 1] + c1 * acc[i][1], 0.f);
                r4.z = fmaxf(c0 * As[r * KP + tx * 4 + 2] + c1 * acc[i][2], 0.f);
                r4.w = fmaxf(c0 * As[r * KP + tx * 4 + 3] + c1 * acc[i][3], 0.f);
                *(float4*)&g_X[(size_t)row * NHID_ + tx * 4] = r4;
            }
        }
    } else {  // MODE 2: logits + fused log_softmax
        if (active) {
            #pragma unroll
            for (int i = 0; i < 4; i++) {
                int r = ty * 4 + i;
                #pragma unroll
                for (int j = 0; j < 4; j++)
                    Ls[r * NCOL + tx * 4 + j] = acc[i][j] + __ldg(bias + tx * 4 + j);
            }
        }
        __syncthreads();
        if (tid < 64) {
            int row = row0 + tid;
            if (row < M) {
                float mx = -1e30f;
                #pragma unroll
                for (int c = 0; c < NCOL; c++) mx = fmaxf(mx, Ls[tid * NCOL + c]);
                float s = 0.f;
                #pragma unroll
                for (int c = 0; c < NCOL; c++) s += __expf(Ls[tid * NCOL + c] - mx);
                float lse = mx + __logf(s);
                #pragma unroll
                for (int c = 0; c < NCOL; c++)
                    outext[(size_t)row * NCOL + c] = Ls[tid * NCOL + c] - lse;
            }
        }
    }
}

// ---------------- launch ----------------
extern "C" void kernel_launch(void* const* d_in, const int* in_sizes, int n_in,
                              void* d_out, int out_size)
{
    const float* x    = (const float*)d_in[0];
    const float* degE = (const float*)d_in[1];
    const float* degV = (const float*)d_in[2];
    const float* W0   = (const float*)d_in[3];
    const float* b0   = (const float*)d_in[4];
    const float* Ws   = (const float*)d_in[5];
    const float* Wout = (const float*)d_in[6];
    const float* bout = (const float*)d_in[7];
    const int* vertex = (const int*)d_in[8];
    const int* edges  = (const int*)d_in[9];
    float* out = (float*)d_out;

    (void)in_sizes; (void)n_in; (void)out_size;

    const int GB = (N_V + 63) / 64;

    // CSR/CSC build
    zero_cnt_k<<<(N_V + 255) / 256, 256>>>();
    hist_k<<<(NNZ_ + 255) / 256, 256>>>(vertex, edges);
    escale_k<<<(NE_ + 255) / 256, 256>>>(degE);
    scan_excl_k<<<1, 1024>>>(0);
    scan_excl_k<<<1, 1024>>>(1);
    zero_cnt_k<<<(N_V + 255) / 256, 256>>>();
    build_adj_k<<<(NNZ_ + 255) / 256, 256>>>(vertex, edges);

    // X = relu(x @ W0 + b0); X0 = X
    gemm_k<128, 64, 0><<<GB, 256>>>(x, W0, b0, nullptr, 0.f, 0.f);

    for (int i = 0; i < NLAYER_; i++) {
        float beta = logf(0.5f / (float)(i + 1) + 1.0f);
        agg_ve_k<<<NE_, 64>>>();
        agg_ev_k<<<N_V, 64>>>(degV);
        gemm_k<64, 64, 1><<<GB, 256>>>(nullptr, Ws + (size_t)i * NHID_ * NHID_,
                                       nullptr, nullptr, 1.0f - beta, beta);
    }

    // log_softmax(X @ Wout + bout)
    gemm_k<64, 40, 2><<<GB, 256>>>(nullptr, Wout, bout, out, 0.f, 0.f);
}